// round 12
// baseline (speedup 1.0000x reference)
#include <cuda_runtime.h>
#include <cuda_bf16.h>

// Grouping: out[B,G,H] = sum_{t=0..3} values[(b*G+g)*4+t] * feats[b, g*4+t, :]
// B=8, S=4096, H=1024, G=1024, TOKENS_PER_GROUP=4 -> 8192 output rows.
// Final (R1 operating point): plain LDG.128 x4 per thread, regs=32, 64-warp
// occupancy, default L2 policy, 1 row/CTA. This configuration measured the best
// HBM draw (6.14 TB/s, 77.6% of spec) and best time across 7 experiments;
// streaming hints, persistence, pipelining, wide CTAs, and evict_last residency
// were each tried and each regressed or was neutral. Traffic (128 MB read +
// 32 MB write) is irreducible; the kernel runs at the mixed-stream HBM floor.

static constexpr int H_VEC = 1024 / 4;  // 256 float4 per row

__global__ __launch_bounds__(256, 8)
void grouping_kernel(const float4* __restrict__ feats,
                     const float* __restrict__ values,
                     float4* __restrict__ out) {
    const int r = blockIdx.x;            // output row: b*G + g
    const int c = threadIdx.x;           // float4 column, 0..255

    const size_t src_base = (size_t)r * 4 * H_VEC;
    const float v0 = __ldg(&values[4 * r + 0]);
    const float v1 = __ldg(&values[4 * r + 1]);
    const float v2 = __ldg(&values[4 * r + 2]);
    const float v3 = __ldg(&values[4 * r + 3]);

    // 4 independent 16B loads -> MLP=4 per thread, 64 warps/SM aggregate
    const float4 a = __ldg(&feats[src_base + 0 * H_VEC + c]);
    const float4 b = __ldg(&feats[src_base + 1 * H_VEC + c]);
    const float4 d = __ldg(&feats[src_base + 2 * H_VEC + c]);
    const float4 e = __ldg(&feats[src_base + 3 * H_VEC + c]);

    float4 o;
    o.x = v0 * a.x + v1 * b.x + v2 * d.x + v3 * e.x;
    o.y = v0 * a.y + v1 * b.y + v2 * d.y + v3 * e.y;
    o.z = v0 * a.z + v1 * b.z + v2 * d.z + v3 * e.z;
    o.w = v0 * a.w + v1 * b.w + v2 * d.w + v3 * e.w;

    out[(size_t)r * H_VEC + c] = o;
}

extern "C" void kernel_launch(void* const* d_in, const int* in_sizes, int n_in,
                              void* d_out, int out_size) {
    // metadata order: feats(f32), indices(int), values(f32), num_groups
    const float4* feats  = (const float4*)d_in[0];
    const float*  values = (const float*)d_in[2];
    float4*       out    = (float4*)d_out;

    const int B = 8, G = 1024;
    grouping_kernel<<<B * G, 256>>>(feats, values, out);
}

// round 13
// speedup vs baseline: 1.0077x; 1.0077x over previous
#include <cuda_runtime.h>
#include <cuda_bf16.h>

// Grouping: out[B,G,H] = sum_{t=0..3} values[(b*G+g)*4+t] * feats[b, g*4+t, :]
// B=8, S=4096, H=1024, G=1024, TOKENS_PER_GROUP=4 -> 8192 output rows.
//
// FINAL KERNEL — at the hardware floor.
// Plain LDG.128 x4 per thread, regs=32, default L2 policy, 256 thr/CTA,
// 1 output row per CTA. Measured across 3 confirmation rounds:
//   timed 29.18-29.41 us, kernel 24.2-25.3 us, HBM 6.0-6.2 TB/s (78% of spec).
// Traffic (128 MB read + 32 MB write) is irreducible; 6.2 TB/s is the mixed
// read/write stream ceiling on this part. Falsified levers (each regressed or
// neutral in a dedicated round): streaming/evict hints (R2, R8), software
// pipelining + persistent grid at regs>32 (R4), 1024-thread CTAs + __stcs (R5),
// values float4 packing (R9/R11). TMA == LDG at the LTS cap; DRAM is binding.

static constexpr int H_VEC = 1024 / 4;  // 256 float4 per row

__global__ __launch_bounds__(256, 8)
void grouping_kernel(const float4* __restrict__ feats,
                     const float* __restrict__ values,
                     float4* __restrict__ out) {
    const int r = blockIdx.x;            // output row: b*G + g
    const int c = threadIdx.x;           // float4 column, 0..255

    const size_t src_base = (size_t)r * 4 * H_VEC;
    const float v0 = __ldg(&values[4 * r + 0]);
    const float v1 = __ldg(&values[4 * r + 1]);
    const float v2 = __ldg(&values[4 * r + 2]);
    const float v3 = __ldg(&values[4 * r + 3]);

    // 4 independent 16B loads -> MLP=4 per thread, 64 warps/SM aggregate
    const float4 a = __ldg(&feats[src_base + 0 * H_VEC + c]);
    const float4 b = __ldg(&feats[src_base + 1 * H_VEC + c]);
    const float4 d = __ldg(&feats[src_base + 2 * H_VEC + c]);
    const float4 e = __ldg(&feats[src_base + 3 * H_VEC + c]);

    float4 o;
    o.x = v0 * a.x + v1 * b.x + v2 * d.x + v3 * e.x;
    o.y = v0 * a.y + v1 * b.y + v2 * d.y + v3 * e.y;
    o.z = v0 * a.z + v1 * b.z + v2 * d.z + v3 * e.z;
    o.w = v0 * a.w + v1 * b.w + v2 * d.w + v3 * e.w;

    out[(size_t)r * H_VEC + c] = o;
}

extern "C" void kernel_launch(void* const* d_in, const int* in_sizes, int n_in,
                              void* d_out, int out_size) {
    // metadata order: feats(f32), indices(int), values(f32), num_groups
    const float4* feats  = (const float4*)d_in[0];
    const float*  values = (const float*)d_in[2];
    float4*       out    = (float4*)d_out;

    const int B = 8, G = 1024;
    grouping_kernel<<<B * G, 256>>>(feats, values, out);
}